// round 13
// baseline (speedup 1.0000x reference)
#include <cuda_runtime.h>
#include <cuda_fp16.h>
#include <cstdint>

#define NT 256
#define MT 64

// ---- smem byte offsets ----
#define OFF_A     0          // A fp16: 64 rows x 1024B = 65536
#define OFF_B     65536      // 4 ring slots x 16384 = 65536
#define OFF_BIAS  131072     // 512 f32 interleaved biases
#define OFF_TREL  133120     // 64 f32
#define OFF_HP    133376     // 64 x 8B ptr
#define OFF_OP    133888
#define OFF_FP    134400
#define OFF_WT    134912     // 128 f32
#define OFF_BT    135424     // 128 f32
#define SMEM_TOTAL 135936

// fused, gate-interleaved, swizzled fp16 B image: [tgn][32 chunks][16K]
__device__ unsigned char g_Bimg[2u * 32u * 16384u];

__device__ __forceinline__ uint32_t smem_u32(const void* p) {
    uint32_t a;
    asm("{ .reg .u64 t; cvta.to.shared.u64 t, %1; cvt.u32.u64 %0, t; }" : "=r"(a) : "l"(p));
    return a;
}
__device__ __forceinline__ void cpasync16(uint32_t s, const void* g) {
    asm volatile("cp.async.cg.shared.global [%0], [%1], 16;" :: "r"(s), "l"(g));
}
#define CP_COMMIT() asm volatile("cp.async.commit_group;" ::: "memory")
#define CP_WAIT2()  asm volatile("cp.async.wait_group 2;" ::: "memory")
#define CP_WAIT0()  asm volatile("cp.async.wait_group 0;" ::: "memory")

__device__ __forceinline__ void ldm4(uint32_t* r, uint32_t a) {
    asm volatile("ldmatrix.sync.aligned.m8n8.x4.shared.b16 {%0,%1,%2,%3}, [%4];"
        : "=r"(r[0]), "=r"(r[1]), "=r"(r[2]), "=r"(r[3]) : "r"(a));
}
__device__ __forceinline__ void ldm4t(uint32_t* r, uint32_t a) {
    asm volatile("ldmatrix.sync.aligned.m8n8.x4.trans.shared.b16 {%0,%1,%2,%3}, [%4];"
        : "=r"(r[0]), "=r"(r[1]), "=r"(r[2]), "=r"(r[3]) : "r"(a));
}
__device__ __forceinline__ void mma16816(float* c, const uint32_t* a, uint32_t b0, uint32_t b1) {
    asm volatile("mma.sync.aligned.m16n8k16.row.col.f32.f16.f16.f32 "
        "{%0,%1,%2,%3}, {%4,%5,%6,%7}, {%8,%9}, {%0,%1,%2,%3};"
        : "+f"(c[0]), "+f"(c[1]), "+f"(c[2]), "+f"(c[3])
        : "r"(a[0]), "r"(a[1]), "r"(a[2]), "r"(a[3]), "r"(b0), "r"(b1));
}
__device__ __forceinline__ float sigm(float x) { return 1.0f / (1.0f + __expf(-x)); }

// ---- prep: fused, gate-interleaved, swizzled fp16 B image ----
// col c = 4*u + gate. gate0: Wih_r + Whh_r(k<128); gate1: Wih_z + Whh_z(k<128);
// gate2: Wih_n; gate3: Whh_n (k<128, else 0).
__global__ void prep_B(const float* __restrict__ Wih_m, const float* __restrict__ Whh_m,
                       const float* __restrict__ Wih_p, const float* __restrict__ Whh_p) {
    unsigned gid = blockIdx.x * blockDim.x + threadIdx.x;
    if (gid >= 2u * 32u * 16u * 512u) return;
    int n = gid & 511;
    int kl = (gid >> 9) & 15;
    int chunk = (gid >> 13) & 31;
    int tgn = gid >> 18;
    int k = chunk * 16 + kl;
    int u = n >> 2, g = n & 3;
    const float* Wih = tgn ? Wih_p : Wih_m;
    const float* Whh = tgn ? Whh_p : Whh_m;
    float v;
    if (g == 0)      v = Wih[(size_t)u * 512 + k] + (k < 128 ? Whh[(size_t)u * 128 + k] : 0.0f);
    else if (g == 1) v = Wih[(size_t)(128 + u) * 512 + k] + (k < 128 ? Whh[(size_t)(128 + u) * 128 + k] : 0.0f);
    else if (g == 2) v = Wih[(size_t)(256 + u) * 512 + k];
    else             v = (k < 128) ? Whh[(size_t)(256 + u) * 128 + k] : 0.0f;
    unsigned off = (unsigned)kl * 1024u + (((unsigned)n * 2u) ^ (((unsigned)kl & 7u) << 4));
    size_t base = ((size_t)tgn * 32 + chunk) * 16384u;
    *(__half*)(g_Bimg + base + off) = __float2half_rn(v);
}

__device__ __forceinline__ void issue_chunk(uint32_t smb, int slot,
                                            const unsigned char* img, int chunk, int tid) {
    uint32_t d = smb + OFF_B + slot * 16384 + tid * 16;
    const unsigned char* s = img + (size_t)chunk * 16384u + tid * 16;
    #pragma unroll
    for (int r = 0; r < 4; r++) cpasync16(d + r * 4096, s + r * 4096);
}

__global__ __launch_bounds__(NT, 1) void tgn_hmma_kernel(
    const int* __restrict__ n_id,
    const float* __restrict__ memory_, const float* __restrict__ pos_mem,
    const float* __restrict__ pos_emb,
    const float* __restrict__ raw_s, const float* __restrict__ raw_d,
    const int* __restrict__ other_s, const int* __restrict__ other_d,
    const int* __restrict__ t_s, const int* __restrict__ t_d,
    const int* __restrict__ last_update,
    const float* __restrict__ w_tm, const float* __restrict__ b_tm,
    const float* __restrict__ w_tp, const float* __restrict__ b_tp,
    const float* __restrict__ bih_m, const float* __restrict__ bhh_m,
    const float* __restrict__ bih_p, const float* __restrict__ bhh_p,
    float* __restrict__ out, int N)
{
    extern __shared__ unsigned char sm[];
    const uint32_t smb = smem_u32(sm);
    const int tid = threadIdx.x, wid = tid >> 5, lane = tid & 31;
    const int tgn = blockIdx.y;
    const int row0 = blockIdx.x * MT;

    const float* mem = tgn ? pos_mem : memory_;
    const float* bih = tgn ? bih_p : bih_m;
    const float* bhh = tgn ? bhh_p : bhh_m;
    const float* wt  = tgn ? w_tp : w_tm;
    const float* bt  = tgn ? b_tp : b_tm;
    const unsigned char* img = g_Bimg + (size_t)tgn * 32u * 16384u;

    // ---- phase 0: metadata, biases, time params ----
    if (tid < 64) {
        const int i = row0 + tid;
        const int nid = n_id[i];
        const int ts = t_s[i], td = t_d[i];
        const bool pick = (ts >= td);
        const int od = other_d[i];
        const int o = pick ? other_s[i] : od;
        ((float*)(sm + OFF_TREL))[tid] = (float)((pick ? ts : td) - last_update[nid]);
        ((const float**)(sm + OFF_HP))[tid] = mem + (size_t)nid * 128;
        ((const float**)(sm + OFF_OP))[tid] = mem + (size_t)o * 128;
        const float* f;
        if (tgn == 0) f = (pick ? raw_s : raw_d) + (size_t)i * 128;
        else          f = pos_emb + (size_t)(pick ? nid : od) * 128;
        ((const float**)(sm + OFF_FP))[tid] = f;
    }
    if (tid < 128) {
        ((float*)(sm + OFF_WT))[tid] = wt[tid];
        ((float*)(sm + OFF_BT))[tid] = bt[tid];
    }
    #pragma unroll
    for (int cb = 0; cb < 2; cb++) {   // interleaved biases: c = 4u+g
        const int c = tid + cb * 256, u = c >> 2, g = c & 3;
        float bv;
        if (g == 0)      bv = bih[u] + bhh[u];
        else if (g == 1) bv = bih[128 + u] + bhh[128 + u];
        else if (g == 2) bv = bih[256 + u];
        else             bv = bhh[256 + u];
        ((float*)(sm + OFF_BIAS))[c] = bv;
    }

    // prefetch B chunks 0,1,2 into ring slots 0,1,2
    issue_chunk(smb, 0, img, 0, tid); CP_COMMIT();
    issue_chunk(smb, 1, img, 1, tid); CP_COMMIT();
    issue_chunk(smb, 2, img, 2, tid); CP_COMMIT();
    __syncthreads();

    // ---- phase 1: build A (fp16, swizzled rows): 64 rows x 512 k ----
    {
        const int r = tid & 63;          // row
        const int sec = tid >> 6;        // 0:h 1:other 2:feat 3:time (128 k each)
        const float* src =
            (sec == 0) ? ((const float**)(sm + OFF_HP))[r] :
            (sec == 1) ? ((const float**)(sm + OFF_OP))[r] :
            (sec == 2) ? ((const float**)(sm + OFF_FP))[r] : nullptr;
        const float trel = ((const float*)(sm + OFF_TREL))[r];
        const float* wts = (const float*)(sm + OFF_WT);
        const float* bts = (const float*)(sm + OFF_BT);
        #pragma unroll 4
        for (int kk = 0; kk < 128; kk += 4) {
            const int k = sec * 128 + kk;
            float4 v;
            if (sec < 3) v = *(const float4*)(src + kk);
            else {
                v.x = cosf(fmaf(trel, wts[kk + 0], bts[kk + 0]));
                v.y = cosf(fmaf(trel, wts[kk + 1], bts[kk + 1]));
                v.z = cosf(fmaf(trel, wts[kk + 2], bts[kk + 2]));
                v.w = cosf(fmaf(trel, wts[kk + 3], bts[kk + 3]));
            }
            __half2 h01 = __floats2half2_rn(v.x, v.y);
            __half2 h23 = __floats2half2_rn(v.z, v.w);
            const unsigned off = (unsigned)r * 1024u + (((unsigned)k * 2u) ^ (((unsigned)r & 7u) << 4));
            uint2 hv;
            hv.x = *(unsigned*)&h01; hv.y = *(unsigned*)&h23;
            *(uint2*)(sm + OFF_A + off) = hv;
        }
    }
    __syncthreads();

    // ---- mainloop: 32 K-chunks of 16, 4-slot ring, warp tile 64m x 64n ----
    const int wc = wid;                  // col block (64 cols), 8 warps x 64 = 512
    const int lrow = lane & 15;
    const int khalf = (lane & 16) ? 16 : 0;   // byte offset (8 k)

    float acc[4][8][4];
    #pragma unroll
    for (int a = 0; a < 4; a++)
        #pragma unroll
        for (int b = 0; b < 8; b++)
            #pragma unroll
            for (int c = 0; c < 4; c++) acc[a][b][c] = 0.0f;

    uint32_t aad[4];
    unsigned asw[4];
    #pragma unroll
    for (int mf = 0; mf < 4; mf++) {
        const unsigned arow = (unsigned)(mf * 16 + lrow);
        aad[mf] = smb + OFF_A + arow * 1024u;
        asw[mf] = (arow & 7u) << 4;
    }
    const unsigned bswl = ((unsigned)lrow & 7u) << 4;
    const uint32_t brow = (unsigned)lrow * 1024u;
    const unsigned wc64 = (unsigned)(wc * 64);

    for (int ks = 0; ks < 32; ks++) {
        CP_WAIT2();                       // chunk ks resident
        __syncthreads();                  // all warps done with slot (ks+3)&3's old data
        const uint32_t bufb = smb + OFF_B + (ks & 3) * 16384;
        const unsigned kb = (unsigned)(ks * 32 + khalf);

        uint32_t ah[4][4];
        #pragma unroll
        for (int mf = 0; mf < 4; mf++) ldm4(ah[mf], aad[mf] + (kb ^ asw[mf]));
        #pragma unroll
        for (int jj = 0; jj < 4; jj++) {
            const unsigned nbyte = (wc64 + jj * 16u) * 2u + (unsigned)khalf;
            uint32_t bh[4];
            ldm4t(bh, bufb + brow + (nbyte ^ bswl));
            #pragma unroll
            for (int mf = 0; mf < 4; mf++) {
                mma16816(acc[mf][2 * jj],     ah[mf], bh[0], bh[1]);
                mma16816(acc[mf][2 * jj + 1], ah[mf], bh[2], bh[3]);
            }
        }
        if (ks + 3 < 32) issue_chunk(smb, (ks + 3) & 3, img, ks + 3, tid);
        CP_COMMIT();                      // uniform group counting (empty groups ok)
    }
    CP_WAIT0();
    __syncthreads();

    // ---- epilogue: GRU gates via lane-pair exchange; exact h from gmem ----
    {
        const int g = lane >> 2, t = lane & 3;
        float* stg = (float*)(sm + OFF_B);           // 64 x 132 f32 staging (33.8KB)
        const float* biasA = (const float*)(sm + OFF_BIAS);
        const float** hpp = (const float**)(sm + OFF_HP);
        #pragma unroll
        for (int mf = 0; mf < 4; mf++) {
            const int mbase = mf * 16;
            #pragma unroll
            for (int j = 0; j < 8; j++) {
                const int c0 = wc * 64 + j * 8 + 2 * t;
                const float b0v = biasA[c0], b1v = biasA[c0 + 1];
                const float v0 = acc[mf][j][0] + b0v;
                const float v1 = acc[mf][j][1] + b1v;
                const float v2 = acc[mf][j][2] + b0v;
                const float v3 = acc[mf][j][3] + b1v;
                const float p0 = __shfl_xor_sync(0xFFFFFFFFu, v0, 1);
                const float p1 = __shfl_xor_sync(0xFFFFFFFFu, v1, 1);
                const float p2 = __shfl_xor_sync(0xFFFFFFFFu, v2, 1);
                const float p3 = __shfl_xor_sync(0xFFFFFFFFu, v3, 1);
                const int m = mbase + g + ((t & 1) ? 8 : 0);
                const int u = wc * 16 + 2 * j + (t >> 1);
                float rv, zv, iv, hnv;
                if (t & 1) { rv = p2; zv = p3; iv = v2; hnv = v3; }
                else       { rv = v0; zv = v1; iv = p0; hnv = p1; }
                const float rg = sigm(rv);
                const float zg = sigm(zv);
                const float ng = tanhf(fmaf(rg, hnv, iv));
                const float h = hpp[m][u];            // exact fp32 h from gmem (L2)
                stg[m * 132 + u] = fmaf(zg, h - ng, ng);
            }
        }
    }
    __syncthreads();

    // coalesced output
    {
        float* og = out + (size_t)tgn * N * 128 + (size_t)row0 * 128;
        const float* stg = (const float*)(sm + OFF_B);
        #pragma unroll 4
        for (int idx = tid; idx < MT * 128; idx += NT)
            og[idx] = stg[(idx >> 7) * 132 + (idx & 127)];
    }
    if (tgn == 0 && tid < 64) {
        const int i = row0 + tid;
        const int ts = t_s[i], td = t_d[i];
        out[(size_t)2 * N * 128 + i] = (float)(ts > td ? ts : td);
    }
}

extern "C" void kernel_launch(void* const* d_in, const int* in_sizes, int n_in,
                              void* d_out, int out_size)
{
    const int*   n_id    = (const int*)  d_in[0];
    const float* memory_ = (const float*)d_in[1];
    const float* pos_mem = (const float*)d_in[2];
    const float* pos_emb = (const float*)d_in[3];
    const float* raw_s   = (const float*)d_in[4];
    const float* raw_d   = (const float*)d_in[5];
    const int*   other_s = (const int*)  d_in[6];
    const int*   other_d = (const int*)  d_in[7];
    const int*   t_s     = (const int*)  d_in[8];
    const int*   t_d     = (const int*)  d_in[9];
    const int*   last_up = (const int*)  d_in[10];
    const float* w_tm    = (const float*)d_in[11];
    const float* b_tm    = (const float*)d_in[12];
    const float* w_tp    = (const float*)d_in[13];
    const float* b_tp    = (const float*)d_in[14];
    const float* Wih_m   = (const float*)d_in[15];
    const float* Whh_m   = (const float*)d_in[16];
    const float* bih_m   = (const float*)d_in[17];
    const float* bhh_m   = (const float*)d_in[18];
    const float* Wih_p   = (const float*)d_in[19];
    const float* Whh_p   = (const float*)d_in[20];
    const float* bih_p   = (const float*)d_in[21];
    const float* bhh_p   = (const float*)d_in[22];

    const int N = in_sizes[0];

    cudaFuncSetAttribute(tgn_hmma_kernel,
                         cudaFuncAttributeMaxDynamicSharedMemorySize, SMEM_TOTAL);

    prep_B<<<(2 * 32 * 16 * 512 + 255) / 256, 256>>>(Wih_m, Whh_m, Wih_p, Whh_p);

    dim3 grid(N / MT, 2);
    tgn_hmma_kernel<<<grid, NT, SMEM_TOTAL>>>(
        n_id, memory_, pos_mem, pos_emb, raw_s, raw_d,
        other_s, other_d, t_s, t_d, last_up,
        w_tm, b_tm, w_tp, b_tp,
        bih_m, bhh_m, bih_p, bhh_p,
        (float*)d_out, N);
}

// round 14
// speedup vs baseline: 1.4210x; 1.4210x over previous
#include <cuda_runtime.h>
#include <cuda_fp16.h>
#include <cstdint>

#define NT 256
#define MT 32

// ---- smem byte offsets ----
#define OFF_A     0          // A fp16: 32 rows x 1024B = 32768
#define OFF_B     32768      // 8 warps x 4 slots x 2048B = 65536
#define OFF_BIAS  98304      // 512 f32 interleaved biases
#define OFF_TREL  100352     // 32 f32
#define OFF_HP    100480     // 32 x 8B ptr
#define OFF_OP    100736
#define OFF_FP    100992
#define OFF_WT    101248     // 128 f32
#define OFF_BT    101760     // 128 f32
#define SMEM_TOTAL 102272

// fused, gate-interleaved, swizzled fp16 B image: [tgn][32 chunks][16K]
__device__ unsigned char g_Bimg[2u * 32u * 16384u];

__device__ __forceinline__ uint32_t smem_u32(const void* p) {
    uint32_t a;
    asm("{ .reg .u64 t; cvta.to.shared.u64 t, %1; cvt.u32.u64 %0, t; }" : "=r"(a) : "l"(p));
    return a;
}
__device__ __forceinline__ void cpasync16(uint32_t s, const void* g) {
    asm volatile("cp.async.cg.shared.global [%0], [%1], 16;" :: "r"(s), "l"(g));
}
#define CP_COMMIT() asm volatile("cp.async.commit_group;" ::: "memory")
#define CP_WAIT2()  asm volatile("cp.async.wait_group 2;" ::: "memory")
#define CP_WAIT0()  asm volatile("cp.async.wait_group 0;" ::: "memory")

__device__ __forceinline__ void ldm4(uint32_t* r, uint32_t a) {
    asm volatile("ldmatrix.sync.aligned.m8n8.x4.shared.b16 {%0,%1,%2,%3}, [%4];"
        : "=r"(r[0]), "=r"(r[1]), "=r"(r[2]), "=r"(r[3]) : "r"(a));
}
__device__ __forceinline__ void ldm4t(uint32_t* r, uint32_t a) {
    asm volatile("ldmatrix.sync.aligned.m8n8.x4.trans.shared.b16 {%0,%1,%2,%3}, [%4];"
        : "=r"(r[0]), "=r"(r[1]), "=r"(r[2]), "=r"(r[3]) : "r"(a));
}
__device__ __forceinline__ void mma16816(float* c, const uint32_t* a, uint32_t b0, uint32_t b1) {
    asm volatile("mma.sync.aligned.m16n8k16.row.col.f32.f16.f16.f32 "
        "{%0,%1,%2,%3}, {%4,%5,%6,%7}, {%8,%9}, {%0,%1,%2,%3};"
        : "+f"(c[0]), "+f"(c[1]), "+f"(c[2]), "+f"(c[3])
        : "r"(a[0]), "r"(a[1]), "r"(a[2]), "r"(a[3]), "r"(b0), "r"(b1));
}
__device__ __forceinline__ float sigm(float x) { return 1.0f / (1.0f + __expf(-x)); }

// ---- prep: fused, gate-interleaved, swizzled fp16 B image ----
// col c = 4*u + gate. gate0: Wih_r + Whh_r(k<128); gate1: Wih_z + Whh_z(k<128);
// gate2: Wih_n; gate3: Whh_n (k<128, else 0).
__global__ void prep_B(const float* __restrict__ Wih_m, const float* __restrict__ Whh_m,
                       const float* __restrict__ Wih_p, const float* __restrict__ Whh_p) {
    unsigned gid = blockIdx.x * blockDim.x + threadIdx.x;
    if (gid >= 2u * 32u * 16u * 512u) return;
    int n = gid & 511;
    int kl = (gid >> 9) & 15;
    int chunk = (gid >> 13) & 31;
    int tgn = gid >> 18;
    int k = chunk * 16 + kl;
    int u = n >> 2, g = n & 3;
    const float* Wih = tgn ? Wih_p : Wih_m;
    const float* Whh = tgn ? Whh_p : Whh_m;
    float v;
    if (g == 0)      v = Wih[(size_t)u * 512 + k] + (k < 128 ? Whh[(size_t)u * 128 + k] : 0.0f);
    else if (g == 1) v = Wih[(size_t)(128 + u) * 512 + k] + (k < 128 ? Whh[(size_t)(128 + u) * 128 + k] : 0.0f);
    else if (g == 2) v = Wih[(size_t)(256 + u) * 512 + k];
    else             v = (k < 128) ? Whh[(size_t)(256 + u) * 128 + k] : 0.0f;
    unsigned off = (unsigned)kl * 1024u + (((unsigned)n * 2u) ^ (((unsigned)kl & 7u) << 4));
    size_t base = ((size_t)tgn * 32 + chunk) * 16384u;
    *(__half*)(g_Bimg + base + off) = __float2half_rn(v);
}

// per-warp B slice copy: warp wc's 128B column block of each of 16 rows (2KB)
// dst strip slot layout: row kl at +kl*128, preserving within-block swizzle.
__device__ __forceinline__ void issue_slice(uint32_t strip_slot,
                                            const unsigned char* imgc,
                                            int wc, int lane) {
    #pragma unroll
    for (int r = 0; r < 4; r++) {
        const int s = lane + 32 * r;          // 0..127
        const int kl = s >> 3;
        const int off = (s & 7) * 16;
        cpasync16(strip_slot + (unsigned)s * 16u,
                  imgc + (unsigned)kl * 1024u + (unsigned)wc * 128u + (unsigned)off);
    }
}

__global__ __launch_bounds__(NT, 2) void tgn_hmma_kernel(
    const int* __restrict__ n_id,
    const float* __restrict__ memory_, const float* __restrict__ pos_mem,
    const float* __restrict__ pos_emb,
    const float* __restrict__ raw_s, const float* __restrict__ raw_d,
    const int* __restrict__ other_s, const int* __restrict__ other_d,
    const int* __restrict__ t_s, const int* __restrict__ t_d,
    const int* __restrict__ last_update,
    const float* __restrict__ w_tm, const float* __restrict__ b_tm,
    const float* __restrict__ w_tp, const float* __restrict__ b_tp,
    const float* __restrict__ bih_m, const float* __restrict__ bhh_m,
    const float* __restrict__ bih_p, const float* __restrict__ bhh_p,
    float* __restrict__ out, int N)
{
    extern __shared__ unsigned char sm[];
    const uint32_t smb = smem_u32(sm);
    const int tid = threadIdx.x, wid = tid >> 5, lane = tid & 31;
    const int tgn = blockIdx.y;
    const int row0 = blockIdx.x * MT;

    const float* mem = tgn ? pos_mem : memory_;
    const float* bih = tgn ? bih_p : bih_m;
    const float* bhh = tgn ? bhh_p : bhh_m;
    const float* wt  = tgn ? w_tp : w_tm;
    const float* bt  = tgn ? b_tp : b_tm;
    const unsigned char* img = g_Bimg + (size_t)tgn * 32u * 16384u;

    // ---- phase 0: metadata, biases, time params ----
    if (tid < 32) {
        const int i = row0 + tid;
        const int nid = n_id[i];
        const int ts = t_s[i], td = t_d[i];
        const bool pick = (ts >= td);
        const int od = other_d[i];
        const int o = pick ? other_s[i] : od;
        ((float*)(sm + OFF_TREL))[tid] = (float)((pick ? ts : td) - last_update[nid]);
        ((const float**)(sm + OFF_HP))[tid] = mem + (size_t)nid * 128;
        ((const float**)(sm + OFF_OP))[tid] = mem + (size_t)o * 128;
        const float* f;
        if (tgn == 0) f = (pick ? raw_s : raw_d) + (size_t)i * 128;
        else          f = pos_emb + (size_t)(pick ? nid : od) * 128;
        ((const float**)(sm + OFF_FP))[tid] = f;
    }
    if (tid < 128) {
        ((float*)(sm + OFF_WT))[tid] = wt[tid];
        ((float*)(sm + OFF_BT))[tid] = bt[tid];
    }
    #pragma unroll
    for (int cb = 0; cb < 2; cb++) {   // interleaved biases: c = 4u+g
        const int c = tid + cb * 256, u = c >> 2, g = c & 3;
        float bv;
        if (g == 0)      bv = bih[u] + bhh[u];
        else if (g == 1) bv = bih[128 + u] + bhh[128 + u];
        else if (g == 2) bv = bih[256 + u];
        else             bv = bhh[256 + u];
        ((float*)(sm + OFF_BIAS))[c] = bv;
    }
    __syncthreads();

    // ---- phase 1: build A (fp16, swizzled rows) ----
    {
        const int r = tid & 31;          // row
        const int p = tid >> 5;          // 0..7 -> k block of 64
        const int sec = p >> 1;          // 0:h 1:other 2:feat 3:time
        const int idx0 = (p & 1) * 64;
        const float* src =
            (sec == 0) ? ((const float**)(sm + OFF_HP))[r] :
            (sec == 1) ? ((const float**)(sm + OFF_OP))[r] :
            (sec == 2) ? ((const float**)(sm + OFF_FP))[r] : nullptr;
        const float trel = ((const float*)(sm + OFF_TREL))[r];
        const float* wts = (const float*)(sm + OFF_WT);
        const float* bts = (const float*)(sm + OFF_BT);
        #pragma unroll 4
        for (int kk = 0; kk < 64; kk += 4) {
            const int k = p * 64 + kk;
            float4 v;
            if (sec < 3) v = *(const float4*)(src + idx0 + kk);
            else {
                const int q = idx0 + kk;
                v.x = cosf(fmaf(trel, wts[q + 0], bts[q + 0]));
                v.y = cosf(fmaf(trel, wts[q + 1], bts[q + 1]));
                v.z = cosf(fmaf(trel, wts[q + 2], bts[q + 2]));
                v.w = cosf(fmaf(trel, wts[q + 3], bts[q + 3]));
            }
            __half2 h01 = __floats2half2_rn(v.x, v.y);
            __half2 h23 = __floats2half2_rn(v.z, v.w);
            const unsigned off = (unsigned)r * 1024u + (((unsigned)k * 2u) ^ (((unsigned)r & 7u) << 4));
            uint2 hv;
            hv.x = *(unsigned*)&h01; hv.y = *(unsigned*)&h23;
            *(uint2*)(sm + OFF_A + off) = hv;
        }
    }
    __syncthreads();   // A visible to all warps; mainloop reads A read-only

    // ---- mainloop: per-warp pipeline, NO CTA barriers ----
    const int wc = wid;                  // col block (64 cols), warp tile 32m x 64n
    const int lrow = lane & 15;
    const int khalf = (lane & 16) ? 16 : 0;   // byte offset (8 k)
    const uint32_t strip = smb + OFF_B + (unsigned)wid * 8192u;   // 4 slots x 2KB

    float acc[2][8][4];
    #pragma unroll
    for (int a = 0; a < 2; a++)
        #pragma unroll
        for (int b = 0; b < 8; b++)
            #pragma unroll
            for (int c = 0; c < 4; c++) acc[a][b][c] = 0.0f;

    const unsigned arow0 = (unsigned)lrow;
    const unsigned arow1 = arow0 + 16;
    const unsigned asw0 = (arow0 & 7u) << 4;
    const unsigned asw1 = (arow1 & 7u) << 4;
    const uint32_t aad0 = smb + OFF_A + arow0 * 1024u;
    const uint32_t aad1 = smb + OFF_A + arow1 * 1024u;
    const unsigned bsw = ((unsigned)lrow & 7u) << 4;
    const uint32_t browp = strip;        // + slot*2048 + lrow*128

    // per-warp prefetch chunks 0,1,2
    issue_slice(strip + 0 * 2048, img + 0 * 16384, wc, lane); CP_COMMIT();
    issue_slice(strip + 1 * 2048, img + 1 * 16384, wc, lane); CP_COMMIT();
    issue_slice(strip + 2 * 2048, img + 2 * 16384, wc, lane); CP_COMMIT();

    for (int ks = 0; ks < 32; ks++) {
        CP_WAIT2();                       // this warp's chunk ks resident
        __syncwarp();
        const uint32_t bufb = strip + (unsigned)(ks & 3) * 2048u + (unsigned)lrow * 128u;
        const unsigned kb = (unsigned)(ks * 32 + khalf);

        uint32_t ah[2][4];
        ldm4(ah[0], aad0 + (kb ^ asw0));
        ldm4(ah[1], aad1 + (kb ^ asw1));
        #pragma unroll
        for (int jj = 0; jj < 4; jj++) {
            const unsigned nb = (unsigned)(jj * 32) + (unsigned)khalf;
            uint32_t bh[4];
            ldm4t(bh, bufb + (nb ^ bsw));
            mma16816(acc[0][2 * jj],     ah[0], bh[0], bh[1]);
            mma16816(acc[0][2 * jj + 1], ah[0], bh[2], bh[3]);
            mma16816(acc[1][2 * jj],     ah[1], bh[0], bh[1]);
            mma16816(acc[1][2 * jj + 1], ah[1], bh[2], bh[3]);
        }
        if (ks + 3 < 32)
            issue_slice(strip + (unsigned)((ks + 3) & 3) * 2048u, img + (size_t)(ks + 3) * 16384u, wc, lane);
        CP_COMMIT();                      // uniform per-warp group counting
    }
    CP_WAIT0();
    __syncthreads();   // all strips idle before reuse as staging

    // ---- epilogue: GRU gates via lane-pair exchange; exact h from gmem ----
    {
        const int g = lane >> 2, t = lane & 3;
        float* stg = (float*)(sm + OFF_B);           // 32 x 132 f32 staging
        const float* biasA = (const float*)(sm + OFF_BIAS);
        const float** hpp = (const float**)(sm + OFF_HP);
        #pragma unroll
        for (int mf = 0; mf < 2; mf++) {
            const int mbase = mf * 16;
            #pragma unroll
            for (int j = 0; j < 8; j++) {
                const int c0 = wc * 64 + j * 8 + 2 * t;
                const float b0v = biasA[c0], b1v = biasA[c0 + 1];
                const float v0 = acc[mf][j][0] + b0v;
                const float v1 = acc[mf][j][1] + b1v;
                const float v2 = acc[mf][j][2] + b0v;
                const float v3 = acc[mf][j][3] + b1v;
                const float p0 = __shfl_xor_sync(0xFFFFFFFFu, v0, 1);
                const float p1 = __shfl_xor_sync(0xFFFFFFFFu, v1, 1);
                const float p2 = __shfl_xor_sync(0xFFFFFFFFu, v2, 1);
                const float p3 = __shfl_xor_sync(0xFFFFFFFFu, v3, 1);
                const int m = mbase + g + ((t & 1) ? 8 : 0);
                const int u = wc * 16 + 2 * j + (t >> 1);
                float rv, zv, iv, hnv;
                if (t & 1) { rv = p2; zv = p3; iv = v2; hnv = v3; }
                else       { rv = v0; zv = v1; iv = p0; hnv = p1; }
                const float rg = sigm(rv);
                const float zg = sigm(zv);
                const float ng = tanhf(fmaf(rg, hnv, iv));
                const float h = hpp[m][u];            // exact fp32 h from gmem (L2)
                stg[m * 132 + u] = fmaf(zg, h - ng, ng);
            }
        }
    }
    __syncthreads();

    // coalesced output
    {
        float* og = out + (size_t)tgn * N * 128 + (size_t)row0 * 128;
        const float* stg = (const float*)(sm + OFF_B);
        #pragma unroll 4
        for (int idx = tid; idx < MT * 128; idx += NT)
            og[idx] = stg[(idx >> 7) * 132 + (idx & 127)];
    }
    if (tgn == 0 && tid < 32) {
        const int i = row0 + tid;
        const int ts = t_s[i], td = t_d[i];
        out[(size_t)2 * N * 128 + i] = (float)(ts > td ? ts : td);
    }
}

extern "C" void kernel_launch(void* const* d_in, const int* in_sizes, int n_in,
                              void* d_out, int out_size)
{
    const int*   n_id    = (const int*)  d_in[0];
    const float* memory_ = (const float*)d_in[1];
    const float* pos_mem = (const float*)d_in[2];
    const float* pos_emb = (const float*)d_in[3];
    const float* raw_s   = (const float*)d_in[4];
    const float* raw_d   = (const float*)d_in[5];
    const int*   other_s = (const int*)  d_in[6];
    const int*   other_d = (const int*)  d_in[7];
    const int*   t_s     = (const int*)  d_in[8];
    const int*   t_d     = (const int*)  d_in[9];
    const int*   last_up = (const int*)  d_in[10];
    const float* w_tm    = (const float*)d_in[11];
    const float* b_tm    = (const float*)d_in[12];
    const float* w_tp    = (const float*)d_in[13];
    const float* b_tp    = (const float*)d_in[14];
    const float* Wih_m   = (const float*)d_in[15];
    const float* Whh_m   = (const float*)d_in[16];
    const float* bih_m   = (const float*)d_in[17];
    const float* bhh_m   = (const float*)d_in[18];
    const float* Wih_p   = (const float*)d_in[19];
    const float* Whh_p   = (const float*)d_in[20];
    const float* bih_p   = (const float*)d_in[21];
    const float* bhh_p   = (const float*)d_in[22];

    const int N = in_sizes[0];

    cudaFuncSetAttribute(tgn_hmma_kernel,
                         cudaFuncAttributeMaxDynamicSharedMemorySize, SMEM_TOTAL);

    prep_B<<<(2 * 32 * 16 * 512 + 255) / 256, 256>>>(Wih_m, Whh_m, Wih_p, Whh_p);

    dim3 grid(N / MT, 2);
    tgn_hmma_kernel<<<grid, NT, SMEM_TOTAL>>>(
        n_id, memory_, pos_mem, pos_emb, raw_s, raw_d,
        other_s, other_d, t_s, t_d, last_up,
        w_tm, b_tm, w_tp, b_tp,
        bih_m, bhh_m, bih_p, bhh_p,
        (float*)d_out, N);
}